// round 9
// baseline (speedup 1.0000x reference)
#include <cuda_runtime.h>
#include <cstdint>

// Problem constants (ViT-B/16 @384: b=32, n=577, c=768, H=12, d=64, keep=0.7)
#define B   32
#define N   577
#define C   768
#define HH  12
#define DD  64
#define NK  576
#define FT  404
#define SCALE 0.125f

// Output layout: x | index | ind | class_attention | final_tokens (float32)
#define OFF_X      0ll
#define OFF_INDEX  14180352ll
#define OFF_IND    24109056ll
#define OFF_CA     24121984ll
#define OFF_FT     24140416ll

#define FULLM 0xFFFFFFFFu

// k_dots tiling: 6 c-slices of 128, 5 j-tiles of 128, 16-c stage tiles
#define CS   6
#define CSL  128
#define CT   16
#define JB   128
#define JT   640
#define JPAD 132

// ---------------- scratch ----------------------------------------------------
__device__ float g_qp[6][B * C];
__device__ float g_q[B * C];
__device__ float g_u[B * HH * C];
__device__ float g_beta[B * HH];
__device__ float g_dotsp[CS * B * HH * JT];
__device__ int   g_ind[B * FT];

// ---------------- K1a: qproj partials. grid (6,4), block 768 ----------------
// Each block: one 128-cc slice s, 8 batches. W row loaded ONCE per 8 batches.
__global__ void __launch_bounds__(768) k_qprojp(const float* __restrict__ x,
                                                const float* __restrict__ W) {
    int s = blockIdx.x, bg = blockIdx.y, col = threadIdx.x;
    __shared__ float xs[8][128];
    for (int f = col; f < 8 * 128; f += 768) {
        int bl = f >> 7, cc = f & 127;
        xs[bl][cc] = x[(size_t)(bg * 8 + bl) * N * C + s * 128 + cc];
    }
    __syncthreads();
    float acc[8];
#pragma unroll
    for (int bb = 0; bb < 8; bb++) acc[bb] = 0.f;
#pragma unroll 8
    for (int i = 0; i < 128; i++) {
        float w = W[(size_t)(s * 128 + i) * 3 * C + col];
#pragma unroll
        for (int bb = 0; bb < 8; bb++) acc[bb] = fmaf(xs[bb][i], w, acc[bb]);
    }
#pragma unroll
    for (int bb = 0; bb < 8; bb++)
        g_qp[s][(bg * 8 + bb) * C + col] = acc[bb];
}

// ---------------- K1b: q = sum partials + bias. grid 32, block 768 ----------
__global__ void k_qreduce(const float* __restrict__ bq) {
    int b = blockIdx.x, col = threadIdx.x;
    float acc = bq[col];
#pragma unroll
    for (int s = 0; s < 6; s++) acc += g_qp[s][b * C + col];
    g_q[b * C + col] = acc;
}

// ---------------- K2: u[b,h,c] = sum_d Wk[c,h*64+d]*q[b,h,d]; beta ----------
// grid 48 blocks (16 cc each), block 384 threads (= 32 b * 12 h)
__global__ void __launch_bounds__(384) k_uproj(const float* __restrict__ W,
                                               const float* __restrict__ bqkv) {
    int cc0 = blockIdx.x * 16;
    int tid = threadIdx.x;
    int b = tid / HH, h = tid % HH;

    float q[DD];
    const float4* qp = (const float4*)&g_q[b * C + h * DD];
#pragma unroll
    for (int i = 0; i < DD / 4; i++) {
        float4 v = qp[i];
        q[4 * i + 0] = v.x; q[4 * i + 1] = v.y; q[4 * i + 2] = v.z; q[4 * i + 3] = v.w;
    }

    __shared__ float w[16][C];
    // stage 16 Wk rows (cols 768..1535) via float4
    for (int f = tid; f < 16 * (C / 4); f += 384) {
        int row = f / (C / 4), cf = f % (C / 4);
        ((float4*)w[row])[cf] =
            *(const float4*)&W[(size_t)(cc0 + row) * 3 * C + C + cf * 4];
    }
    __syncthreads();
#pragma unroll
    for (int s = 0; s < 16; s++) {
        float acc = 0.f;
#pragma unroll
        for (int d = 0; d < DD; d++) acc = fmaf(w[s][h * DD + d], q[d], acc);
        g_u[(size_t)(b * HH + h) * C + cc0 + s] = acc;
    }
    if (blockIdx.x == 0) {
        float acc = 0.f;
#pragma unroll
        for (int d = 0; d < DD; d++) acc = fmaf(bqkv[C + h * DD + d], q[d], acc);
        g_beta[tid] = acc;
    }
}

// ---------------- K3: dots partials. grid (32, CS, 5), block 128 ------------
// Double-buffered smem, register prefetch, ONE barrier per c-tile.
__global__ void __launch_bounds__(128) k_dots(const float* __restrict__ x,
                                              float* __restrict__ out) {
    int b = blockIdx.x, cs = blockIdx.y, jt = blockIdx.z, t = threadIdx.x;
    int c0 = cs * CSL;
    int jbase = jt * JB;

    __shared__ float xsT[2][CT][JPAD];   // double-buffered transposed x tile
    __shared__ float usT[CSL][12];       // transposed u slice [c][h]

    // stage u^T once (visible after the first in-loop barrier)
    for (int i = t; i < CSL * HH; i += 128) {
        int h = i / CSL, cc = i % CSL;
        usT[cc][h] = g_u[((size_t)b * HH + h) * C + c0 + cc];
    }

    int jr0 = t >> 2,            fc0 = t & 3;
    int jr1 = (t + 128) >> 2,    fc1 = (t + 128) & 3;
    int jr2 = (t + 256) >> 2,    fc2 = (t + 256) & 3;
    int jr3 = (t + 384) >> 2,    fc3 = (t + 384) & 3;
    int jj0 = jbase + jr0, jj1 = jbase + jr1, jj2 = jbase + jr2, jj3 = jbase + jr3;

    float4 pv0, pv1, pv2, pv3;
    const float4 z4 = make_float4(0.f, 0.f, 0.f, 0.f);

#define LOAD_TILE(ct_) do {                                                    \
        pv0 = (jj0 < N) ? *(const float4*)&x[((size_t)b*N+jj0)*C + c0 + (ct_) + fc0*4] : z4; \
        pv1 = (jj1 < N) ? *(const float4*)&x[((size_t)b*N+jj1)*C + c0 + (ct_) + fc1*4] : z4; \
        pv2 = (jj2 < N) ? *(const float4*)&x[((size_t)b*N+jj2)*C + c0 + (ct_) + fc2*4] : z4; \
        pv3 = (jj3 < N) ? *(const float4*)&x[((size_t)b*N+jj3)*C + c0 + (ct_) + fc3*4] : z4; \
    } while (0)

    float acc[12];
#pragma unroll
    for (int h = 0; h < 12; h++) acc[h] = 0.f;

    LOAD_TILE(0);

    for (int tile = 0; tile < CSL / CT; tile++) {
        int buf = tile & 1;
        int ct = tile * CT;
        if (jj0 < N) *(float4*)&out[OFF_X + ((size_t)b*N+jj0)*C + c0 + ct + fc0*4] = pv0;
        if (jj1 < N) *(float4*)&out[OFF_X + ((size_t)b*N+jj1)*C + c0 + ct + fc1*4] = pv1;
        if (jj2 < N) *(float4*)&out[OFF_X + ((size_t)b*N+jj2)*C + c0 + ct + fc2*4] = pv2;
        if (jj3 < N) *(float4*)&out[OFF_X + ((size_t)b*N+jj3)*C + c0 + ct + fc3*4] = pv3;
        {
            int cc = fc0 * 4;
            xsT[buf][cc+0][jr0] = pv0.x; xsT[buf][cc+1][jr0] = pv0.y;
            xsT[buf][cc+2][jr0] = pv0.z; xsT[buf][cc+3][jr0] = pv0.w;
            cc = fc1 * 4;
            xsT[buf][cc+0][jr1] = pv1.x; xsT[buf][cc+1][jr1] = pv1.y;
            xsT[buf][cc+2][jr1] = pv1.z; xsT[buf][cc+3][jr1] = pv1.w;
            cc = fc2 * 4;
            xsT[buf][cc+0][jr2] = pv2.x; xsT[buf][cc+1][jr2] = pv2.y;
            xsT[buf][cc+2][jr2] = pv2.z; xsT[buf][cc+3][jr2] = pv2.w;
            cc = fc3 * 4;
            xsT[buf][cc+0][jr3] = pv3.x; xsT[buf][cc+1][jr3] = pv3.y;
            xsT[buf][cc+2][jr3] = pv3.z; xsT[buf][cc+3][jr3] = pv3.w;
        }
        if (tile + 1 < CSL / CT) LOAD_TILE(ct + CT);
        __syncthreads();
#pragma unroll
        for (int cc = 0; cc < CT; cc++) {
            const float4 u0 = *(const float4*)&usT[ct + cc][0];
            const float4 u1 = *(const float4*)&usT[ct + cc][4];
            const float4 u2 = *(const float4*)&usT[ct + cc][8];
            float xv = xsT[buf][cc][t];
            acc[0]  = fmaf(xv, u0.x, acc[0]);
            acc[1]  = fmaf(xv, u0.y, acc[1]);
            acc[2]  = fmaf(xv, u0.z, acc[2]);
            acc[3]  = fmaf(xv, u0.w, acc[3]);
            acc[4]  = fmaf(xv, u1.x, acc[4]);
            acc[5]  = fmaf(xv, u1.y, acc[5]);
            acc[6]  = fmaf(xv, u1.z, acc[6]);
            acc[7]  = fmaf(xv, u1.w, acc[7]);
            acc[8]  = fmaf(xv, u2.x, acc[8]);
            acc[9]  = fmaf(xv, u2.y, acc[9]);
            acc[10] = fmaf(xv, u2.z, acc[10]);
            acc[11] = fmaf(xv, u2.w, acc[11]);
        }
    }
#undef LOAD_TILE

    int jme = jbase + t;
    if (jme < N) {
#pragma unroll
        for (int h = 0; h < 12; h++)
            g_dotsp[((size_t)(cs * B + b) * HH + h) * JT + jme] = acc[h];
    }
}

// ---------------- K4: softmax + head-mean + top-k + ind ---------------------
// grid 32, block 768 (= 12 heads x 64 threads). Uniform barriers only.
__global__ void __launch_bounds__(768) k_finish(float* __restrict__ out,
                                                const float* __restrict__ keep_rate) {
    int b = blockIdx.x, tid = threadIdx.x;
    int h = tid >> 6, s = tid & 63;
    int lane = tid & 31, warp = tid >> 5;

    __shared__ float redm[24];
    __shared__ float reds[24];
    __shared__ float pr[12][580];
    __shared__ float4 vals4[NK / 4];
    __shared__ int wcnt[24];
    float* vals = (float*)vals4;

    float beta = g_beta[b * HH + h];

    float d[10];
    float m = -1e30f;
#pragma unroll
    for (int k = 0; k < 10; k++) {
        int j = s + 64 * k;
        float v = -1e30f;
        if (j < N) {
            float sum = beta;
#pragma unroll
            for (int cs = 0; cs < CS; cs++)
                sum += g_dotsp[((size_t)(cs * B + b) * HH + h) * JT + j];
            v = SCALE * sum;
        }
        d[k] = v;
        m = fmaxf(m, v);
    }
    for (int o = 16; o; o >>= 1) m = fmaxf(m, __shfl_xor_sync(FULLM, m, o));
    if (lane == 0) redm[warp] = m;
    __syncthreads();
    m = fmaxf(redm[2 * h], redm[2 * h + 1]);

    float e[10];
    float sm = 0.f;
#pragma unroll
    for (int k = 0; k < 10; k++) {
        e[k] = (d[k] > -1e29f) ? __expf(d[k] - m) : 0.f;
        sm += e[k];
    }
    for (int o = 16; o; o >>= 1) sm += __shfl_xor_sync(FULLM, sm, o);
    if (lane == 0) reds[warp] = sm;
    __syncthreads();
    float inv = 1.f / (reds[2 * h] + reds[2 * h + 1]);

#pragma unroll
    for (int k = 0; k < 10; k++) {
        int j = s + 64 * k;
        if (j < N) pr[h][j] = e[k] * inv;
    }
    __syncthreads();

    if (tid < NK) {
        float c = 0.f;
#pragma unroll
        for (int hh = 0; hh < 12; hh++) c += pr[hh][tid + 1];
        c *= (1.f / 12.f);
        vals[tid] = c;
        out[OFF_CA + (size_t)b * NK + tid] = c;
    }
    __syncthreads();

    int K = (int)ceilf(keep_rate[0] * (float)NK);   // 404

    int i = (tid < NK) ? tid : 0;
    float vi = vals[i];
    int rank = 0;
#pragma unroll 4
    for (int jq = 0; jq < NK / 4; jq++) {
        float4 v = vals4[jq];
        int j = jq * 4;
        rank += (v.x > vi) || (v.x == vi && (j + 0) < i);
        rank += (v.y > vi) || (v.y == vi && (j + 1) < i);
        rank += (v.z > vi) || (v.z == vi && (j + 2) < i);
        rank += (v.w > vi) || (v.w == vi && (j + 3) < i);
    }
    bool sel = (tid < NK) && (rank < K);
    unsigned mm = __ballot_sync(FULLM, sel);
    if (lane == 0) wcnt[warp] = __popc(mm);
    __syncthreads();
    int base = 0;
    for (int w = 0; w < warp; w++) base += wcnt[w];
    int pos = base + __popc(mm & ((1u << lane) - 1u));
    if (sel) {
        out[OFF_IND + (size_t)b * FT + pos] = (float)i;
        g_ind[b * FT + pos] = i;
    }
    if (b == 0 && tid == 0) out[OFF_FT] = (float)K;
}

// ---------------- K5: index broadcast, full-chip ----------------------------
__global__ void k_index(float* __restrict__ out) {
    int t = threadIdx.x;
    int r0 = blockIdx.x * 4;
    float4* op = (float4*)(out + OFF_INDEX) + (size_t)r0 * (C / 4);
#pragma unroll
    for (int k = 0; k < 3; k++) {
        int idx = t + 256 * k;
        int r = idx / (C / 4);
        int col = idx - r * (C / 4);
        float v = (float)g_ind[r0 + r];
        op[(size_t)r * (C / 4) + col] = make_float4(v, v, v, v);
    }
}

// ---------------- launch -----------------------------------------------------
extern "C" void kernel_launch(void* const* d_in, const int* in_sizes, int n_in,
                              void* d_out, int out_size) {
    const float* x    = (const float*)d_in[0];
    const float* kr   = (const float*)d_in[1];
    const float* Wqkv = (const float*)d_in[2];
    const float* bqkv = (const float*)d_in[3];
    float* out = (float*)d_out;

    k_qprojp<<<dim3(6, 4), 768>>>(x, Wqkv);
    k_qreduce<<<B, C>>>(bqkv);
    k_uproj<<<48, 384>>>(Wqkv, bqkv);
    k_dots<<<dim3(B, CS, 5), 128>>>(x, out);   // also copies x -> out
    k_finish<<<B, 768>>>(out, kr);
    k_index<<<(B * FT) / 4, 256>>>(out);
}

// round 10
// speedup vs baseline: 1.3504x; 1.3504x over previous
#include <cuda_runtime.h>
#include <cstdint>

// Problem constants (ViT-B/16 @384: b=32, n=577, c=768, H=12, d=64, keep=0.7)
#define B   32
#define N   577
#define C   768
#define HH  12
#define DD  64
#define NK  576
#define FT  404
#define SCALE 0.125f

// Output layout: x | index | ind | class_attention | final_tokens (float32)
#define OFF_X      0ll
#define OFF_INDEX  14180352ll
#define OFF_IND    24109056ll
#define OFF_CA     24121984ll
#define OFF_FT     24140416ll

#define FULLM 0xFFFFFFFFu

// k_dots tiling: 6 c-slices of 128, 5 j-tiles of 128, 32-c stage tiles
#define CS   6
#define CSL  128
#define CT   32
#define JB   128
#define JT   640
#define JPAD 129     // conflict-free: bank = 4*(l&7) + (l>>3) + const

// ---------------- scratch ----------------------------------------------------
__device__ float g_qp[6][B * C];
__device__ float g_q[B * C];
__device__ float g_u[B * HH * C];
__device__ float g_beta[B * HH];
__device__ float g_dotsp[CS * B * HH * JT];
__device__ int   g_ind[B * FT];

// ---------------- K1a: qproj partials. grid (32,6), block 768 (R8 config) ---
__global__ void __launch_bounds__(768) k_qprojp(const float* __restrict__ x,
                                                const float* __restrict__ W) {
    int b = blockIdx.x, s = blockIdx.y, col = threadIdx.x;
    __shared__ float xs[128];
    if (col < 128) xs[col] = x[(size_t)b * N * C + s * 128 + col];
    __syncthreads();
    float acc = 0.f;
#pragma unroll 16
    for (int i = 0; i < 128; i++)
        acc = fmaf(xs[i], W[(size_t)(s * 128 + i) * 3 * C + col], acc);
    g_qp[s][b * C + col] = acc;
}

// ---------------- K1b: q = sum partials + bias. grid 32, block 768 ----------
__global__ void k_qreduce(const float* __restrict__ bq) {
    int b = blockIdx.x, col = threadIdx.x;
    float acc = bq[col];
#pragma unroll
    for (int s = 0; s < 6; s++) acc += g_qp[s][b * C + col];
    g_q[b * C + col] = acc;
}

// ---------------- K2: u[b,h,c]; beta. grid 192 (4 cc), block 384 (R8) -------
__global__ void k_uproj(const float* __restrict__ W,
                        const float* __restrict__ bqkv) {
    int cc0 = blockIdx.x * 4;
    int tid = threadIdx.x;
    int b = tid / HH, h = tid % HH;

    float q[DD];
    const float4* qp = (const float4*)&g_q[b * C + h * DD];
#pragma unroll
    for (int i = 0; i < DD / 4; i++) {
        float4 v = qp[i];
        q[4 * i + 0] = v.x; q[4 * i + 1] = v.y; q[4 * i + 2] = v.z; q[4 * i + 3] = v.w;
    }

    __shared__ float w[4][C];
#pragma unroll
    for (int s = 0; s < 4; s++) {
        w[s][tid]       = W[(size_t)(cc0 + s) * 3 * C + C + tid];
        w[s][tid + 384] = W[(size_t)(cc0 + s) * 3 * C + C + tid + 384];
    }
    __syncthreads();
#pragma unroll
    for (int s = 0; s < 4; s++) {
        float acc = 0.f;
#pragma unroll
        for (int d = 0; d < DD; d++) acc = fmaf(w[s][h * DD + d], q[d], acc);
        g_u[(size_t)(b * HH + h) * C + cc0 + s] = acc;
    }
    if (blockIdx.x == 0) {
        float acc = 0.f;
#pragma unroll
        for (int d = 0; d < DD; d++) acc = fmaf(bqkv[C + h * DD + d], q[d], acc);
        g_beta[tid] = acc;
    }
}

// ---------------- K3: dots partials. grid (32, CS, 5), block 128 ------------
// CT=32 double-buffered tiles; 4 barriers total; register prefetch depth 1.
__global__ void __launch_bounds__(128) k_dots(const float* __restrict__ x,
                                              float* __restrict__ out) {
    int b = blockIdx.x, cs = blockIdx.y, jt = blockIdx.z, t = threadIdx.x;
    int c0 = cs * CSL;
    int jbase = jt * JB;

    __shared__ float xsT[2][CT][JPAD];   // 2*32*129*4 = 33 KB
    __shared__ float usT[CSL][12];       // 6 KB

    // stage u^T once (visible after the first in-loop barrier)
    for (int i = t; i < CSL * HH; i += 128) {
        int h = i / CSL, cc = i % CSL;
        usT[cc][h] = g_u[((size_t)b * HH + h) * C + c0 + cc];
    }

    // per-thread staging coords: 8 float4 per 32c x 128j tile
    int jr[8], fc[8], jj[8];
#pragma unroll
    for (int k = 0; k < 8; k++) {
        int f = t + 128 * k;
        jr[k] = f >> 3; fc[k] = f & 7; jj[k] = jbase + jr[k];
    }

    float4 pv[8];
    const float4 z4 = make_float4(0.f, 0.f, 0.f, 0.f);

#define LOAD_TILE(ct_) do {                                                     \
        _Pragma("unroll")                                                       \
        for (int k = 0; k < 8; k++)                                             \
            pv[k] = (jj[k] < N)                                                 \
                ? *(const float4*)&x[((size_t)b*N+jj[k])*C + c0 + (ct_) + fc[k]*4] \
                : z4;                                                           \
    } while (0)

    float acc[12];
#pragma unroll
    for (int h = 0; h < 12; h++) acc[h] = 0.f;

    LOAD_TILE(0);

#pragma unroll
    for (int tile = 0; tile < CSL / CT; tile++) {
        int buf = tile & 1;
        int ct = tile * CT;
        // fused x -> out copy + smem staging of the prefetched tile
#pragma unroll
        for (int k = 0; k < 8; k++) {
            if (jj[k] < N)
                *(float4*)&out[OFF_X + ((size_t)b*N+jj[k])*C + c0 + ct + fc[k]*4] = pv[k];
            int cc = fc[k] * 4;
            xsT[buf][cc + 0][jr[k]] = pv[k].x;
            xsT[buf][cc + 1][jr[k]] = pv[k].y;
            xsT[buf][cc + 2][jr[k]] = pv[k].z;
            xsT[buf][cc + 3][jr[k]] = pv[k].w;
        }
        if (tile + 1 < CSL / CT) LOAD_TILE(ct + CT);
        __syncthreads();
#pragma unroll
        for (int cc = 0; cc < CT; cc++) {
            const float4 u0 = *(const float4*)&usT[ct + cc][0];
            const float4 u1 = *(const float4*)&usT[ct + cc][4];
            const float4 u2 = *(const float4*)&usT[ct + cc][8];
            float xv = xsT[buf][cc][t];
            acc[0]  = fmaf(xv, u0.x, acc[0]);
            acc[1]  = fmaf(xv, u0.y, acc[1]);
            acc[2]  = fmaf(xv, u0.z, acc[2]);
            acc[3]  = fmaf(xv, u0.w, acc[3]);
            acc[4]  = fmaf(xv, u1.x, acc[4]);
            acc[5]  = fmaf(xv, u1.y, acc[5]);
            acc[6]  = fmaf(xv, u1.z, acc[6]);
            acc[7]  = fmaf(xv, u1.w, acc[7]);
            acc[8]  = fmaf(xv, u2.x, acc[8]);
            acc[9]  = fmaf(xv, u2.y, acc[9]);
            acc[10] = fmaf(xv, u2.z, acc[10]);
            acc[11] = fmaf(xv, u2.w, acc[11]);
        }
    }
#undef LOAD_TILE

    int jme = jbase + t;
    if (jme < N) {
#pragma unroll
        for (int h = 0; h < 12; h++)
            g_dotsp[((size_t)(cs * B + b) * HH + h) * JT + jme] = acc[h];
    }
}

// ---------------- K4: softmax + head-mean + top-k + ind ---------------------
// grid 32, block 768 (= 12 heads x 64 threads). Uniform barriers only.
__global__ void __launch_bounds__(768) k_finish(float* __restrict__ out,
                                                const float* __restrict__ keep_rate) {
    int b = blockIdx.x, tid = threadIdx.x;
    int h = tid >> 6, s = tid & 63;
    int lane = tid & 31, warp = tid >> 5;

    __shared__ float redm[24];
    __shared__ float reds[24];
    __shared__ float pr[12][580];
    __shared__ float4 vals4[NK / 4];
    __shared__ int wcnt[24];
    float* vals = (float*)vals4;

    float beta = g_beta[b * HH + h];

    float d[10];
    float m = -1e30f;
#pragma unroll
    for (int k = 0; k < 10; k++) {
        int j = s + 64 * k;
        float v = -1e30f;
        if (j < N) {
            float sum = beta;
#pragma unroll
            for (int cs = 0; cs < CS; cs++)
                sum += g_dotsp[((size_t)(cs * B + b) * HH + h) * JT + j];
            v = SCALE * sum;
        }
        d[k] = v;
        m = fmaxf(m, v);
    }
    for (int o = 16; o; o >>= 1) m = fmaxf(m, __shfl_xor_sync(FULLM, m, o));
    if (lane == 0) redm[warp] = m;
    __syncthreads();
    m = fmaxf(redm[2 * h], redm[2 * h + 1]);

    float e[10];
    float sm = 0.f;
#pragma unroll
    for (int k = 0; k < 10; k++) {
        e[k] = (d[k] > -1e29f) ? __expf(d[k] - m) : 0.f;
        sm += e[k];
    }
    for (int o = 16; o; o >>= 1) sm += __shfl_xor_sync(FULLM, sm, o);
    if (lane == 0) reds[warp] = sm;
    __syncthreads();
    float inv = 1.f / (reds[2 * h] + reds[2 * h + 1]);

#pragma unroll
    for (int k = 0; k < 10; k++) {
        int j = s + 64 * k;
        if (j < N) pr[h][j] = e[k] * inv;
    }
    __syncthreads();

    if (tid < NK) {
        float c = 0.f;
#pragma unroll
        for (int hh = 0; hh < 12; hh++) c += pr[hh][tid + 1];
        c *= (1.f / 12.f);
        vals[tid] = c;
        out[OFF_CA + (size_t)b * NK + tid] = c;
    }
    __syncthreads();

    int K = (int)ceilf(keep_rate[0] * (float)NK);   // 404

    int i = (tid < NK) ? tid : 0;
    float vi = vals[i];
    int rank = 0;
#pragma unroll 4
    for (int jq = 0; jq < NK / 4; jq++) {
        float4 v = vals4[jq];
        int j = jq * 4;
        rank += (v.x > vi) || (v.x == vi && (j + 0) < i);
        rank += (v.y > vi) || (v.y == vi && (j + 1) < i);
        rank += (v.z > vi) || (v.z == vi && (j + 2) < i);
        rank += (v.w > vi) || (v.w == vi && (j + 3) < i);
    }
    bool sel = (tid < NK) && (rank < K);
    unsigned mm = __ballot_sync(FULLM, sel);
    if (lane == 0) wcnt[warp] = __popc(mm);
    __syncthreads();
    int base = 0;
    for (int w = 0; w < warp; w++) base += wcnt[w];
    int pos = base + __popc(mm & ((1u << lane) - 1u));
    if (sel) {
        out[OFF_IND + (size_t)b * FT + pos] = (float)i;
        g_ind[b * FT + pos] = i;
    }
    if (b == 0 && tid == 0) out[OFF_FT] = (float)K;
}

// ---------------- K5: index broadcast, full-chip ----------------------------
__global__ void k_index(float* __restrict__ out) {
    int t = threadIdx.x;
    int r0 = blockIdx.x * 4;
    float4* op = (float4*)(out + OFF_INDEX) + (size_t)r0 * (C / 4);
#pragma unroll
    for (int k = 0; k < 3; k++) {
        int idx = t + 256 * k;
        int r = idx / (C / 4);
        int col = idx - r * (C / 4);
        float v = (float)g_ind[r0 + r];
        op[(size_t)r * (C / 4) + col] = make_float4(v, v, v, v);
    }
}

// ---------------- launch -----------------------------------------------------
extern "C" void kernel_launch(void* const* d_in, const int* in_sizes, int n_in,
                              void* d_out, int out_size) {
    const float* x    = (const float*)d_in[0];
    const float* kr   = (const float*)d_in[1];
    const float* Wqkv = (const float*)d_in[2];
    const float* bqkv = (const float*)d_in[3];
    float* out = (float*)d_out;

    k_qprojp<<<dim3(B, 6), C>>>(x, Wqkv);
    k_qreduce<<<B, C>>>(bqkv);
    k_uproj<<<192, 384>>>(Wqkv, bqkv);
    k_dots<<<dim3(B, CS, 5), 128>>>(x, out);   // also copies x -> out
    k_finish<<<B, 768>>>(out, kr);
    k_index<<<(B * FT) / 4, 256>>>(out);
}